// round 13
// baseline (speedup 1.0000x reference)
#include <cuda_runtime.h>

// MonteCarloPooling: per 2x2 block of x, Gumbel-max categorical sample using
// pre-drawn uniforms u; output = sampled index (0..3) as float.
//
// Equivalence chain:
//   argmax_k [ log(max(b_k,EPS)) - log(-log(clip(u_k))) ]
// = argmax_k [ max(b_k,EPS) / (-log(clip(u_k))) ]          (exp monotone)
// = cross-multiply champion compare (t_k > 0):
//     b_i/t_i > b_j/t_j  <=>  b_i*t_j > b_j*t_i
//
// R12: R8 champion per-thread shape (4 outputs/thread, 8x LDG.128 front
// batch, 48 regs, cross-multiply argmax, accurate logf), re-packed as
// 192 threads x 7 CTAs/SM: 1344 threads = 42 warps/SM at reg cap
// floor(65536/1344)=48 — same register count ptxas chose naturally, so
// identical per-thread code, +5% resident warps -> 336 loads in flight
// vs 320. In-flight loads has been the dur-tracking metric in all 11 rounds.

#define MCP_EPS 1e-12f

// x: (32,64,224,224) fp32; u: (32,64,112,112,4) fp32; out: (32,64,112,112) fp32
static constexpr unsigned PW  = 112;      // pooled width
static constexpr unsigned PH  = 112;      // pooled height
static constexpr unsigned W   = 224;      // input width
static constexpr unsigned GPR = PW / 4;   // 28 float4-groups per pooled row

__device__ __forceinline__ float mcp_pick(float b0, float b1, float b2, float b3,
                                          float4 uu)
{
    // t_k = -log(max(u_k, EPS)) > 0 (accurate logf: argmax-flip budget —
    // MUFU.LG2's absolute error near u->1 would exceed the 1e-3 threshold)
    float t0 = -logf(fmaxf(uu.x, MCP_EPS));
    float t1 = -logf(fmaxf(uu.y, MCP_EPS));
    float t2 = -logf(fmaxf(uu.z, MCP_EPS));
    float t3 = -logf(fmaxf(uu.w, MCP_EPS));

    b0 = fmaxf(b0, MCP_EPS);
    b1 = fmaxf(b1, MCP_EPS);
    b2 = fmaxf(b2, MCP_EPS);
    b3 = fmaxf(b3, MCP_EPS);

    // first-occurrence argmax of b_k/t_k (strict >, jnp.argmax semantics)
    float bb = b0, bt = t0;
    int   idx = 0;
    if (b1 * bt > bb * t1) { bb = b1; bt = t1; idx = 1; }
    if (b2 * bt > bb * t2) { bb = b2; bt = t2; idx = 2; }
    if (b3 * bt > bb * t3) { idx = 3; }
    return (float)idx;
}

__global__ void __launch_bounds__(192, 7)
mcpool_kernel(const float* __restrict__ x,
              const float* __restrict__ u,
              float* __restrict__ out,
              unsigned n4)  // number of 4-output groups
{
    unsigned t = blockIdx.x * blockDim.x + threadIdx.x;
    if (t >= n4) return;

    // 32-bit decomposition, constant divisors -> magic multiplies
    unsigned g   = t % GPR;        // float4-group within pooled row (0..27)
    unsigned row = t / GPR;        // bc*PH + h
    unsigned h   = row % PH;
    unsigned bc  = row / PH;       // fused batch*channel (0..2047)

    // ---- 8-wide LDG.128 front batch ----
    const float*  xbase = x + (bc * (2u * PH) + 2u * h) * W + 8u * g;
    const float4* xr0   = (const float4*)xbase;        // row 2h
    const float4* xr1   = (const float4*)(xbase + W);  // row 2h+1
    const float4* up    = (const float4*)u + (t * 4u);

    float4 a0 = __ldcs(xr0 + 0);   // top row, cols 8g..8g+3
    float4 a1 = __ldcs(xr0 + 1);   // top row, cols 8g+4..8g+7
    float4 c0 = __ldcs(xr1 + 0);   // bottom row
    float4 c1 = __ldcs(xr1 + 1);
    float4 u0 = __ldcs(up + 0);
    float4 u1 = __ldcs(up + 1);
    float4 u2 = __ldcs(up + 2);
    float4 u3 = __ldcs(up + 3);

    // block flatten order k = 2*row_in_block + col_in_block
    float4 res;
    res.x = mcp_pick(a0.x, a0.y, c0.x, c0.y, u0);
    res.y = mcp_pick(a0.z, a0.w, c0.z, c0.w, u1);
    res.z = mcp_pick(a1.x, a1.y, c1.x, c1.y, u2);
    res.w = mcp_pick(a1.z, a1.w, c1.z, c1.w, u3);

    __stcs((float4*)out + t, res);
}

extern "C" void kernel_launch(void* const* d_in, const int* in_sizes, int n_in,
                              void* d_out, int out_size)
{
    const float* x = (const float*)d_in[0];
    const float* u = (const float*)d_in[1];
    float* out = (float*)d_out;

    unsigned n4 = (unsigned)(out_size / 4);   // 6,422,528 groups
    unsigned threads = 192;
    unsigned blocks = (n4 + threads - 1) / threads;
    mcpool_kernel<<<blocks, threads>>>(x, u, out, n4);
}

// round 14
// speedup vs baseline: 1.0053x; 1.0053x over previous
#include <cuda_runtime.h>

// MonteCarloPooling: per 2x2 block of x, Gumbel-max categorical sample using
// pre-drawn uniforms u; output = sampled index (0..3) as float.
//
// Equivalence chain:
//   argmax_k [ log(max(b_k,EPS)) - log(-log(clip(u_k))) ]
// = argmax_k [ max(b_k,EPS) / (-log(clip(u_k))) ]          (exp monotone)
// = cross-multiply champion compare (t_k > 0):
//     b_i/t_i > b_j/t_j  <=>  b_i*t_j > b_j*t_i
//
// R12: R8 champion per-thread shape (4 outputs/thread, 8x LDG.128 front
// batch, 48 regs, cross-multiply argmax, accurate logf), re-packed as
// 192 threads x 7 CTAs/SM: 1344 threads = 42 warps/SM at reg cap
// floor(65536/1344)=48 — same register count ptxas chose naturally, so
// identical per-thread code, +5% resident warps -> 336 loads in flight
// vs 320. In-flight loads has been the dur-tracking metric in all 11 rounds.

#define MCP_EPS 1e-12f

// x: (32,64,224,224) fp32; u: (32,64,112,112,4) fp32; out: (32,64,112,112) fp32
static constexpr unsigned PW  = 112;      // pooled width
static constexpr unsigned PH  = 112;      // pooled height
static constexpr unsigned W   = 224;      // input width
static constexpr unsigned GPR = PW / 4;   // 28 float4-groups per pooled row

__device__ __forceinline__ float mcp_pick(float b0, float b1, float b2, float b3,
                                          float4 uu)
{
    // t_k = -log(max(u_k, EPS)) > 0 (accurate logf: argmax-flip budget —
    // MUFU.LG2's absolute error near u->1 would exceed the 1e-3 threshold)
    float t0 = -logf(fmaxf(uu.x, MCP_EPS));
    float t1 = -logf(fmaxf(uu.y, MCP_EPS));
    float t2 = -logf(fmaxf(uu.z, MCP_EPS));
    float t3 = -logf(fmaxf(uu.w, MCP_EPS));

    b0 = fmaxf(b0, MCP_EPS);
    b1 = fmaxf(b1, MCP_EPS);
    b2 = fmaxf(b2, MCP_EPS);
    b3 = fmaxf(b3, MCP_EPS);

    // first-occurrence argmax of b_k/t_k (strict >, jnp.argmax semantics)
    float bb = b0, bt = t0;
    int   idx = 0;
    if (b1 * bt > bb * t1) { bb = b1; bt = t1; idx = 1; }
    if (b2 * bt > bb * t2) { bb = b2; bt = t2; idx = 2; }
    if (b3 * bt > bb * t3) { idx = 3; }
    return (float)idx;
}

__global__ void __launch_bounds__(192, 7)
mcpool_kernel(const float* __restrict__ x,
              const float* __restrict__ u,
              float* __restrict__ out,
              unsigned n4)  // number of 4-output groups
{
    unsigned t = blockIdx.x * blockDim.x + threadIdx.x;
    if (t >= n4) return;

    // 32-bit decomposition, constant divisors -> magic multiplies
    unsigned g   = t % GPR;        // float4-group within pooled row (0..27)
    unsigned row = t / GPR;        // bc*PH + h
    unsigned h   = row % PH;
    unsigned bc  = row / PH;       // fused batch*channel (0..2047)

    // ---- 8-wide LDG.128 front batch ----
    const float*  xbase = x + (bc * (2u * PH) + 2u * h) * W + 8u * g;
    const float4* xr0   = (const float4*)xbase;        // row 2h
    const float4* xr1   = (const float4*)(xbase + W);  // row 2h+1
    const float4* up    = (const float4*)u + (t * 4u);

    float4 a0 = __ldcs(xr0 + 0);   // top row, cols 8g..8g+3
    float4 a1 = __ldcs(xr0 + 1);   // top row, cols 8g+4..8g+7
    float4 c0 = __ldcs(xr1 + 0);   // bottom row
    float4 c1 = __ldcs(xr1 + 1);
    float4 u0 = __ldcs(up + 0);
    float4 u1 = __ldcs(up + 1);
    float4 u2 = __ldcs(up + 2);
    float4 u3 = __ldcs(up + 3);

    // block flatten order k = 2*row_in_block + col_in_block
    float4 res;
    res.x = mcp_pick(a0.x, a0.y, c0.x, c0.y, u0);
    res.y = mcp_pick(a0.z, a0.w, c0.z, c0.w, u1);
    res.z = mcp_pick(a1.x, a1.y, c1.x, c1.y, u2);
    res.w = mcp_pick(a1.z, a1.w, c1.z, c1.w, u3);

    __stcs((float4*)out + t, res);
}

extern "C" void kernel_launch(void* const* d_in, const int* in_sizes, int n_in,
                              void* d_out, int out_size)
{
    const float* x = (const float*)d_in[0];
    const float* u = (const float*)d_in[1];
    float* out = (float*)d_out;

    unsigned n4 = (unsigned)(out_size / 4);   // 6,422,528 groups
    unsigned threads = 192;
    unsigned blocks = (n4 + threads - 1) / threads;
    mcpool_kernel<<<blocks, threads>>>(x, u, out, n4);
}

// round 15
// speedup vs baseline: 1.0175x; 1.0122x over previous
#include <cuda_runtime.h>

// MonteCarloPooling: per 2x2 block of x, Gumbel-max categorical sample using
// pre-drawn uniforms u; output = sampled index (0..3) as float.
//
// Equivalence chain:
//   argmax_k [ log(max(b_k,EPS)) - log(-log(clip(u_k))) ]
// = argmax_k [ max(b_k,EPS) / (-ln(clip(u_k))) ]            (exp monotone)
// = argmax_k [ max(b_k,EPS) / (-log2(clip(u_k))) ]          (-ln u = ln2 * -log2 u,
//                                                            ln2 > 0 common factor)
// = cross-multiply champion compare (t_k > 0):
//     b_i/t_i > b_j/t_j  <=>  b_i*t_j > b_j*t_i
//
// FINAL (R8 champion + log2f trim):
//  - 4 outputs/thread, 8x LDG.128 front batch, __stcs 128-bit store.
//  - __launch_bounds__(256, 5): 48-reg envelope under which ptxas's latency
//    scheduler keeps the full 8-load batch (every other envelope tried —
//    36/40/64 regs, 192-thread packing, cp.async, asm pinning, v8 loads,
//    8 outputs/thread — measured equal or worse across R2-R14).
//  - log2f instead of logf: argmax invariant (common positive factor ln2),
//    deletes 16 FMULs/thread.
//  - Accurate log (not MUFU approx): keeps argmax flips ~O(1); rel_err ~1e-4.
//  - Measured 6959 GB/s = B300 path-independent LTS chip cap; traffic
//    (925 MB single-touch) is irreducible -> ~131.6 us is the floor.

#define MCP_EPS 1e-12f

// x: (32,64,224,224) fp32; u: (32,64,112,112,4) fp32; out: (32,64,112,112) fp32
static constexpr unsigned PW  = 112;      // pooled width
static constexpr unsigned PH  = 112;      // pooled height
static constexpr unsigned W   = 224;      // input width
static constexpr unsigned GPR = PW / 4;   // 28 float4-groups per pooled row

__device__ __forceinline__ float mcp_pick(float b0, float b1, float b2, float b3,
                                          float4 uu)
{
    // t_k = -log2(max(u_k, EPS)) > 0
    float t0 = -log2f(fmaxf(uu.x, MCP_EPS));
    float t1 = -log2f(fmaxf(uu.y, MCP_EPS));
    float t2 = -log2f(fmaxf(uu.z, MCP_EPS));
    float t3 = -log2f(fmaxf(uu.w, MCP_EPS));

    b0 = fmaxf(b0, MCP_EPS);
    b1 = fmaxf(b1, MCP_EPS);
    b2 = fmaxf(b2, MCP_EPS);
    b3 = fmaxf(b3, MCP_EPS);

    // first-occurrence argmax of b_k/t_k (strict >, jnp.argmax semantics)
    float bb = b0, bt = t0;
    int   idx = 0;
    if (b1 * bt > bb * t1) { bb = b1; bt = t1; idx = 1; }
    if (b2 * bt > bb * t2) { bb = b2; bt = t2; idx = 2; }
    if (b3 * bt > bb * t3) { idx = 3; }
    return (float)idx;
}

__global__ void __launch_bounds__(256, 5)
mcpool_kernel(const float* __restrict__ x,
              const float* __restrict__ u,
              float* __restrict__ out,
              unsigned n4)  // number of 4-output groups
{
    unsigned t = blockIdx.x * blockDim.x + threadIdx.x;
    if (t >= n4) return;

    // 32-bit decomposition, constant divisors -> magic multiplies
    unsigned g   = t % GPR;        // float4-group within pooled row (0..27)
    unsigned row = t / GPR;        // bc*PH + h
    unsigned h   = row % PH;
    unsigned bc  = row / PH;       // fused batch*channel (0..2047)

    // ---- 8-wide LDG.128 front batch ----
    const float*  xbase = x + (bc * (2u * PH) + 2u * h) * W + 8u * g;
    const float4* xr0   = (const float4*)xbase;        // row 2h
    const float4* xr1   = (const float4*)(xbase + W);  // row 2h+1
    const float4* up    = (const float4*)u + (t * 4u);

    float4 a0 = __ldcs(xr0 + 0);   // top row, cols 8g..8g+3
    float4 a1 = __ldcs(xr0 + 1);   // top row, cols 8g+4..8g+7
    float4 c0 = __ldcs(xr1 + 0);   // bottom row
    float4 c1 = __ldcs(xr1 + 1);
    float4 u0 = __ldcs(up + 0);
    float4 u1 = __ldcs(up + 1);
    float4 u2 = __ldcs(up + 2);
    float4 u3 = __ldcs(up + 3);

    // block flatten order k = 2*row_in_block + col_in_block
    float4 res;
    res.x = mcp_pick(a0.x, a0.y, c0.x, c0.y, u0);
    res.y = mcp_pick(a0.z, a0.w, c0.z, c0.w, u1);
    res.z = mcp_pick(a1.x, a1.y, c1.x, c1.y, u2);
    res.w = mcp_pick(a1.z, a1.w, c1.z, c1.w, u3);

    __stcs((float4*)out + t, res);
}

extern "C" void kernel_launch(void* const* d_in, const int* in_sizes, int n_in,
                              void* d_out, int out_size)
{
    const float* x = (const float*)d_in[0];
    const float* u = (const float*)d_in[1];
    float* out = (float*)d_out;

    unsigned n4 = (unsigned)(out_size / 4);   // 6,422,528 groups
    unsigned threads = 256;
    unsigned blocks = (n4 + threads - 1) / threads;
    mcpool_kernel<<<blocks, threads>>>(x, u, out, n4);
}